// round 14
// baseline (speedup 1.0000x reference)
#include <cuda_runtime.h>

// ---------------------------------------------------------------------------
// SupernodeEncoder, SINGLE persistent kernel (one launch — per-kernel fixed
// overhead was dominating the multi-kernel pipelines):
//   Phase 1: per-block SMEM CSR of all M supernodes on a 10^3 grid (cell=2R)
//   Phase 2: point-centric octant match; rare matches fire 9 global REDs
//   gsync   (148-block spin barrier — exact R5-proven config & code)
//   Phase 3: per-supernode mean + fused [8]->[C] projection; resets g_acc
//            after use so every graph replay starts clean.
// 148 blocks x 256 threads: 1 CTA/SM, co-residency guaranteed.
// ---------------------------------------------------------------------------

#define RADIUS2  0.0025f       // 0.05^2
#define H_INV    10.0f         // 1 / (2R)
#define GD_S     10            // supernode-grid cells per axis
#define NCS      1000          // 10^3
#define MMAX_SM  2048          // max supernodes in smem CSR
#define MMAX     4096
#define NTHR     256
#define NBLK     148

// __device__ globals (zero-initialized at module load)
__device__ float g_acc[MMAX * 9];      // [M][9]: sum(pos3,fun5), count
__device__ int   g_bar_count;
__device__ int   g_bar_gen;

__device__ __forceinline__ int cc10(float v) {
    int c = (int)(v * H_INV);
    return min(GD_S - 1, max(0, c));
}

// software grid-wide barrier (all NBLK blocks resident) — R5-proven
__device__ __forceinline__ void gsync() {
    __syncthreads();
    if (threadIdx.x == 0) {
        __threadfence();
        int gen = *(volatile int*)&g_bar_gen;
        if (atomicAdd(&g_bar_count, 1) == NBLK - 1) {
            g_bar_count = 0;
            __threadfence();
            atomicExch(&g_bar_gen, gen + 1);
        } else {
            while (*(volatile int*)&g_bar_gen == gen) { }
        }
        __threadfence();
    }
    __syncthreads();
}

__global__ void __launch_bounds__(NTHR, 1)
fused_kernel(const float* __restrict__ pos,
             const float* __restrict__ fun,
             const int* __restrict__ sidx,
             const float* __restrict__ W,
             const float* __restrict__ b,
             float* __restrict__ out,
             int N, int M, int C) {
    __shared__ int    s_cnt  [NCS];     // per-cell supernode count
    __shared__ int    s_start[NCS];     // per-cell CSR start
    __shared__ int    s_psum [NTHR];    // scan workspace
    __shared__ float4 s_sp   [MMAX_SM]; // packed supernodes (x,y,z,bits(m))

    const int tid  = threadIdx.x;
    const int bid  = blockIdx.x;
    const int gtid = bid * NTHR + tid;
    const int stride = NBLK * NTHR;

    // ---------------- Phase 1: per-block smem CSR build ---------------------
    for (int i = tid; i < NCS; i += NTHR) s_cnt[i] = 0;
    __syncthreads();

    int    mycell[8], myslot[8];
    float4 myval[8];
    int nrec = 0;
    for (int j = tid; j < M && nrec < 8; j += NTHR) {
        int s = sidx[j];
        float sx = pos[3 * s + 0];
        float sy = pos[3 * s + 1];
        float sz = pos[3 * s + 2];
        int cell = (cc10(sz) * GD_S + cc10(sy)) * GD_S + cc10(sx);
        mycell[nrec] = cell;
        myslot[nrec] = atomicAdd(&s_cnt[cell], 1);
        myval [nrec] = make_float4(sx, sy, sz, __int_as_float(j));
        nrec++;
    }
    __syncthreads();

    // block scan over NCS cell counts (4 cells / thread)
    int loc[4], tot = 0;
#pragma unroll
    for (int q = 0; q < 4; q++) {
        int idx = tid * 4 + q;
        int v = (idx < NCS) ? s_cnt[idx] : 0;
        loc[q] = tot;
        tot += v;
    }
    s_psum[tid] = tot;
    __syncthreads();
    for (int o = 1; o < NTHR; o <<= 1) {
        int u = (tid >= o) ? s_psum[tid - o] : 0;
        __syncthreads();
        s_psum[tid] += u;
        __syncthreads();
    }
    int ex = s_psum[tid] - tot;
#pragma unroll
    for (int q = 0; q < 4; q++) {
        int idx = tid * 4 + q;
        if (idx < NCS) s_start[idx] = ex + loc[q];
    }
    __syncthreads();

    for (int r = 0; r < nrec; r++) {
        int slot = s_start[mycell[r]] + myslot[r];
        if (slot < MMAX_SM) s_sp[slot] = myval[r];
    }
    __syncthreads();

    // ---------------- Phase 2: point-centric match --------------------------
    for (int i = gtid; i < N; i += stride) {
        float px = pos[3 * i + 0];
        float py = pos[3 * i + 1];
        float pz = pos[3 * i + 2];

        int cx = cc10(px), cy = cc10(py), cz = cc10(pz);
        int dx = (px > (cx + 0.5f) * 0.1f) ? 1 : -1;
        int dy = (py > (cy + 0.5f) * 0.1f) ? 1 : -1;
        int dz = (pz > (cz + 0.5f) * 0.1f) ? 1 : -1;

        bool floaded = false;
        float f0 = 0.f, f1 = 0.f, f2 = 0.f, f3 = 0.f, f4 = 0.f;

#pragma unroll
        for (int k = 0; k < 8; k++) {
            int x = cx + ((k & 1)        ? dx : 0);
            int y = cy + (((k >> 1) & 1) ? dy : 0);
            int z = cz + ((k >> 2)       ? dz : 0);
            if (((unsigned)x >= GD_S) | ((unsigned)y >= GD_S) |
                ((unsigned)z >= GD_S)) continue;
            int cell = (z * GD_S + y) * GD_S + x;
            int beg = s_start[cell];
            int end = beg + s_cnt[cell];
            for (int q = beg; q < end; q++) {
                float4 e = s_sp[q];
                float ddx = e.x - px;
                float ddy = e.y - py;
                float ddz = e.z - pz;
                float d2 = fmaf(ddx, ddx, fmaf(ddy, ddy, ddz * ddz));
                if (d2 <= RADIUS2) {            // rare: ~0.55 per point
                    if (!floaded) {
                        const float* f = fun + (size_t)i * 5;
                        f0 = f[0]; f1 = f[1]; f2 = f[2]; f3 = f[3]; f4 = f[4];
                        floaded = true;
                    }
                    float* a = g_acc + 9 * __float_as_int(e.w);
                    atomicAdd(a + 0, px);
                    atomicAdd(a + 1, py);
                    atomicAdd(a + 2, pz);
                    atomicAdd(a + 3, f0);
                    atomicAdd(a + 4, f1);
                    atomicAdd(a + 5, f2);
                    atomicAdd(a + 6, f3);
                    atomicAdd(a + 7, f4);
                    atomicAdd(a + 8, 1.f);
                }
            }
        }
    }

    gsync();   // all matches visible

    // ---------------- Phase 3: projection + g_acc reset ---------------------
    __shared__ float s_a[9];
    for (int m = bid; m < M; m += NBLK) {
        if (tid < 9) s_a[tid] = g_acc[m * 9 + tid];
        __syncthreads();

        const float cnt = s_a[8];
        const bool nonempty = (cnt > 0.5f);
        const float inv = nonempty ? (1.f / cnt) : 0.f;
        float mean[8];
#pragma unroll
        for (int k = 0; k < 8; k++) mean[k] = s_a[k] * inv;

        for (int c = tid; c < C; c += NTHR) {
            const float4* w4 = (const float4*)(W + (size_t)c * 8);
            float4 wa = w4[0];
            float4 wb = w4[1];
            float acc = b[c];
            acc = fmaf(mean[0], wa.x, acc);
            acc = fmaf(mean[1], wa.y, acc);
            acc = fmaf(mean[2], wa.z, acc);
            acc = fmaf(mean[3], wa.w, acc);
            acc = fmaf(mean[4], wb.x, acc);
            acc = fmaf(mean[5], wb.y, acc);
            acc = fmaf(mean[6], wb.z, acc);
            acc = fmaf(mean[7], wb.w, acc);
            out[(size_t)m * C + c] = nonempty ? acc : 0.f;
        }
        __syncthreads();                 // everyone done with s_a
        if (tid < 9) g_acc[m * 9 + tid] = 0.f;   // replay-invariant reset
        __syncthreads();
    }
}

// ---------------------------------------------------------------------------
extern "C" void kernel_launch(void* const* d_in, const int* in_sizes, int n_in,
                              void* d_out, int out_size) {
    const float* pos  = (const float*)d_in[0];
    const float* fun  = (const float*)d_in[1];
    const int*   sidx = (const int*)d_in[2];
    const float* W    = (const float*)d_in[3];
    const float* b    = (const float*)d_in[4];
    float* out = (float*)d_out;

    const int N = in_sizes[0] / 3;
    const int M = in_sizes[2];
    const int C = in_sizes[4];

    fused_kernel<<<NBLK, NTHR>>>(pos, fun, sidx, W, b, out, N, M, C);
}

// round 17
// speedup vs baseline: 2.8163x; 2.8163x over previous
#include <cuda_runtime.h>

// ---------------------------------------------------------------------------
// SupernodeEncoder, two PLAIN kernels — structure identical to the R13 pass:
//   K1 match: per-block SMEM CSR of M supernodes on a 10^3 grid (cell = 2R);
//             NEW: batched gather (independent loads) + int2-packed CSR.
//             Octant 8-cell probe per point; rare matches fire 9 global
//             float reductions into g_acc[m].
//   K2 proj:  mean + fused [8]->[C] projection; resets g_acc after use
//             (graph-replay invariant; first call uses module-load zero-init).
// ---------------------------------------------------------------------------

#define RADIUS2  0.0025f       // 0.05^2
#define H_INV    10.0f         // 1 / (2R)
#define GD_S     10            // supernode-grid cells per axis
#define NCS      1000          // 10^3
#define MMAX_SM  2048          // max supernodes in smem CSR (M <= 2048)
#define MMAX     4096
#define NTHR     256
#define NBLK_A   296           // 2 CTAs/SM (R13-proven)

// __device__ globals (zero-initialized at module load)
__device__ float g_acc[MMAX * 9];      // [M][9]: sum(pos3,fun5), count

__device__ __forceinline__ int cc10(float v) {
    int c = (int)(v * H_INV);
    return min(GD_S - 1, max(0, c));
}

// ---------------------------------------------------------------------------
// K1: per-block smem CSR build + point-centric match.
// ---------------------------------------------------------------------------
__global__ void __launch_bounds__(NTHR)
match_kernel(const float* __restrict__ pos,
             const float* __restrict__ fun,
             const int* __restrict__ sidx,
             int N, int M) {
    __shared__ int    s_cnt [NCS];      // histogram workspace
    __shared__ int2   s_cs  [NCS];      // packed (start, count) per cell
    __shared__ int    s_psum[NTHR];     // scan workspace (R13-proven scan)
    __shared__ float4 s_sp  [MMAX_SM];  // packed supernodes (x,y,z,bits(m))

    const int tid    = threadIdx.x;
    const int gtid   = blockIdx.x * NTHR + tid;
    const int stride = NBLK_A * NTHR;

    // ---- build: zero histogram ----
    for (int i = tid; i < NCS; i += NTHR) s_cnt[i] = 0;
    __syncthreads();

    // ---- build: batched gather — all loads in each batch are independent ---
    int b_idx[8];
#pragma unroll
    for (int r = 0; r < 8; r++) {
        int j = tid + r * NTHR;
        b_idx[r] = (j < M) ? sidx[j] : -1;
    }
    float4 b_val[8];
#pragma unroll
    for (int r = 0; r < 8; r++) {
        int s = b_idx[r];
        if (s >= 0) {
            b_val[r] = make_float4(pos[3 * s + 0], pos[3 * s + 1],
                                   pos[3 * s + 2],
                                   __int_as_float(tid + r * NTHR));
        }
    }
    int b_cell[8], b_slot[8];
#pragma unroll
    for (int r = 0; r < 8; r++) {
        if (b_idx[r] >= 0) {
            float4 v = b_val[r];
            b_cell[r] = (cc10(v.z) * GD_S + cc10(v.y)) * GD_S + cc10(v.x);
            b_slot[r] = atomicAdd(&s_cnt[b_cell[r]], 1);
        }
    }
    __syncthreads();

    // ---- build: block scan over NCS cell counts (4/thread) — R13-proven ----
    int loc[4], tot = 0;
#pragma unroll
    for (int q = 0; q < 4; q++) {
        int idx = tid * 4 + q;
        int v = (idx < NCS) ? s_cnt[idx] : 0;
        loc[q] = tot;
        tot += v;
    }
    s_psum[tid] = tot;
    __syncthreads();
    for (int o = 1; o < NTHR; o <<= 1) {
        int u = (tid >= o) ? s_psum[tid - o] : 0;
        __syncthreads();
        s_psum[tid] += u;
        __syncthreads();
    }
    int ex = s_psum[tid] - tot;
#pragma unroll
    for (int q = 0; q < 4; q++) {
        int idx = tid * 4 + q;
        if (idx < NCS) s_cs[idx] = make_int2(ex + loc[q], s_cnt[idx]);
    }
    __syncthreads();

    // ---- build: scatter supernodes into CSR slots ----
#pragma unroll
    for (int r = 0; r < 8; r++) {
        if (b_idx[r] >= 0) {
            int slot = s_cs[b_cell[r]].x + b_slot[r];
            if (slot < MMAX_SM) s_sp[slot] = b_val[r];
        }
    }
    __syncthreads();

    // ---- match: stream this block's slice of points (R13-proven loop) ------
    for (int i = gtid; i < N; i += stride) {
        float px = pos[3 * i + 0];
        float py = pos[3 * i + 1];
        float pz = pos[3 * i + 2];

        int cx = cc10(px), cy = cc10(py), cz = cc10(pz);
        int dx = (px > (cx + 0.5f) * 0.1f) ? 1 : -1;
        int dy = (py > (cy + 0.5f) * 0.1f) ? 1 : -1;
        int dz = (pz > (cz + 0.5f) * 0.1f) ? 1 : -1;

        bool floaded = false;
        float f0 = 0.f, f1 = 0.f, f2 = 0.f, f3 = 0.f, f4 = 0.f;

#pragma unroll
        for (int k = 0; k < 8; k++) {
            int x = cx + ((k & 1)        ? dx : 0);
            int y = cy + (((k >> 1) & 1) ? dy : 0);
            int z = cz + ((k >> 2)       ? dz : 0);
            if (((unsigned)x >= GD_S) | ((unsigned)y >= GD_S) |
                ((unsigned)z >= GD_S)) continue;
            int2 cs = s_cs[(z * GD_S + y) * GD_S + x];   // one LDS.64
            for (int q = cs.x; q < cs.x + cs.y; q++) {
                float4 e = s_sp[q];
                float ddx = e.x - px;
                float ddy = e.y - py;
                float ddz = e.z - pz;
                float d2 = fmaf(ddx, ddx, fmaf(ddy, ddy, ddz * ddz));
                if (d2 <= RADIUS2) {                     // ~0.55 per point
                    if (!floaded) {
                        const float* f = fun + (size_t)i * 5;
                        f0 = f[0]; f1 = f[1]; f2 = f[2]; f3 = f[3]; f4 = f[4];
                        floaded = true;
                    }
                    float* a = g_acc + 9 * __float_as_int(e.w);
                    atomicAdd(a + 0, px);
                    atomicAdd(a + 1, py);
                    atomicAdd(a + 2, pz);
                    atomicAdd(a + 3, f0);
                    atomicAdd(a + 4, f1);
                    atomicAdd(a + 5, f2);
                    atomicAdd(a + 6, f3);
                    atomicAdd(a + 7, f4);
                    atomicAdd(a + 8, 1.f);
                }
            }
        }
    }
}

// ---------------------------------------------------------------------------
// K2: projection (one block per supernode) + g_acc reset — R13-proven.
// ---------------------------------------------------------------------------
__global__ void __launch_bounds__(NTHR)
proj_kernel(const float* __restrict__ W,
            const float* __restrict__ b,
            float* __restrict__ out, int C) {
    const int m = blockIdx.x;
    const int tid = threadIdx.x;

    __shared__ float a[9];
    if (tid < 9) a[tid] = g_acc[m * 9 + tid];
    __syncthreads();

    const float cnt = a[8];
    const bool nonempty = (cnt > 0.5f);
    const float inv = nonempty ? (1.f / cnt) : 0.f;
    float mean[8];
#pragma unroll
    for (int k = 0; k < 8; k++) mean[k] = a[k] * inv;

    for (int c = tid; c < C; c += NTHR) {
        const float4* w4 = (const float4*)(W + (size_t)c * 8);
        float4 wa = w4[0];
        float4 wb = w4[1];
        float acc = b[c];
        acc = fmaf(mean[0], wa.x, acc);
        acc = fmaf(mean[1], wa.y, acc);
        acc = fmaf(mean[2], wa.z, acc);
        acc = fmaf(mean[3], wa.w, acc);
        acc = fmaf(mean[4], wb.x, acc);
        acc = fmaf(mean[5], wb.y, acc);
        acc = fmaf(mean[6], wb.z, acc);
        acc = fmaf(mean[7], wb.w, acc);
        out[(size_t)m * C + c] = nonempty ? acc : 0.f;
    }

    __syncthreads();                     // everyone done with a[]
    if (tid < 9) g_acc[m * 9 + tid] = 0.f;   // replay-invariant reset
}

// ---------------------------------------------------------------------------
extern "C" void kernel_launch(void* const* d_in, const int* in_sizes, int n_in,
                              void* d_out, int out_size) {
    const float* pos  = (const float*)d_in[0];
    const float* fun  = (const float*)d_in[1];
    const int*   sidx = (const int*)d_in[2];
    const float* W    = (const float*)d_in[3];
    const float* b    = (const float*)d_in[4];
    float* out = (float*)d_out;

    const int N = in_sizes[0] / 3;
    const int M = in_sizes[2];
    const int C = in_sizes[4];

    match_kernel<<<NBLK_A, NTHR>>>(pos, fun, sidx, N, M);
    proj_kernel<<<M, NTHR>>>(W, b, out, C);
}